// round 2
// baseline (speedup 1.0000x reference)
#include <cuda_runtime.h>
#include <cstdint>

// ---------------------------------------------------------------------------
// NodeUnpool: out = h_full; out[idx] = h_full[idx]@W1^T + b1 + h_sub@W2^T + b2
//
// Stage 0: 1-thread kernel detects whether idx buffer is int64 or int32
//          (jax silently downcasts int64 -> int32 when x64 is disabled).
// Stage 1: cudaMemcpyAsync D2D copy of h_full -> out (graph-capturable).
// Stage 2: fused dual-GEMM with gather on A (h_full[idx]) and scatter on C,
//          128x128 CTA tile, BK=16, 256 threads, 8x8 per-thread microtile,
//          packed fma.rn.f32x2 (FFMA2) accumulation paired along M.
// ---------------------------------------------------------------------------

#define BM 128
#define BN 128
#define BK 16
#define THREADS 256
#define LDA (BM + 4)   // smem padding: 132 floats, keeps ulonglong2 16B-aligned

__device__ int g_idx_is64;   // 1 if idx buffer holds int64 entries, else int32

__device__ __forceinline__ long long load_idx(const void* idx, int r, int is64) {
    if (is64) return reinterpret_cast<const long long*>(idx)[r];
    return (long long)reinterpret_cast<const int*>(idx)[r];
}

__global__ void detect_idx_kernel(const void* idx, int Mrows, long long Nfull) {
    // Read first few entries as int64. Genuine int64 indices lie in [0, Nfull).
    // int32 data reinterpreted as int64 yields (hi<<32)|lo with hi generally
    // nonzero -> value out of range -> detect int32.
    const long long* p64 = reinterpret_cast<const long long*>(idx);
    int n = Mrows / 2;            // entries readable as int64 even if data is int32
    if (n > 8) n = 8;
    bool ok64 = (n > 0);
    for (int i = 0; i < n; ++i) {
        long long v = p64[i];
        if (v < 0 || v >= Nfull) { ok64 = false; break; }
    }
    g_idx_is64 = ok64 ? 1 : 0;
}

__device__ __forceinline__ unsigned long long pack2(float lo, float hi) {
    unsigned long long r;
    asm("mov.b64 %0, {%1, %2};"
        : "=l"(r) : "r"(__float_as_uint(lo)), "r"(__float_as_uint(hi)));
    return r;
}

__device__ __forceinline__ void unpack2(unsigned long long v, float& lo, float& hi) {
    unsigned int a, b;
    asm("mov.b64 {%0, %1}, %2;" : "=r"(a), "=r"(b) : "l"(v));
    lo = __uint_as_float(a);
    hi = __uint_as_float(b);
}

__device__ __forceinline__ void fma2(unsigned long long& c,
                                     unsigned long long a,
                                     unsigned long long b) {
    asm("fma.rn.f32x2 %0, %1, %2, %0;" : "+l"(c) : "l"(a), "l"(b));
}

__global__ __launch_bounds__(THREADS, 1)
void merge_gemm(const float* __restrict__ h_full,
                const float* __restrict__ h_sub,
                const float* __restrict__ W1,
                const float* __restrict__ b1,
                const float* __restrict__ W2,
                const float* __restrict__ b2,
                const void*  __restrict__ idx,
                float* __restrict__ out,
                int Mrows, int dim)
{
    __shared__ __align__(16) float As[BK][LDA];
    __shared__ __align__(16) float Bs[BK][LDA];

    const int is64  = g_idx_is64;
    const int tid   = threadIdx.x;
    const int tileM = blockIdx.x * BM;
    const int nBase = blockIdx.y * BN;

    // global->smem load mapping: thread covers rows r0 and r0+64, 4 k-cols
    const int r0 = tid >> 2;          // 0..63
    const int c4 = (tid & 3) << 2;    // 0,4,8,12

    // compute mapping: 16x16 thread grid, 8x8 microtile
    const int tx = tid & 15;
    const int ty = tid >> 4;

    bool valid[2];
    const float* aG[2];   // gathered h_full row pointers (pass 0)
    const float* aS[2];   // h_sub row pointers           (pass 1)
#pragma unroll
    for (int h = 0; h < 2; ++h) {
        int r = tileM + r0 + h * 64;
        valid[h] = (r < Mrows);
        long long g = valid[h] ? load_idx(idx, r, is64) : 0;
        int rs = valid[h] ? r : 0;
        aG[h] = h_full + (size_t)g * (size_t)dim;
        aS[h] = h_sub  + (size_t)rs * (size_t)dim;
    }

    // Accumulators: C2[i][j] = packed pair (m = ty*8+2i lo, m = ty*8+2i+1 hi),
    // column n = nBase + tx*8 + j.  0ULL == {0.0f, 0.0f}.
    unsigned long long C2[4][8];
#pragma unroll
    for (int i = 0; i < 4; ++i)
#pragma unroll
        for (int j = 0; j < 8; ++j) C2[i][j] = 0ULL;

#pragma unroll 1
    for (int pass = 0; pass < 2; ++pass) {
        const float* Wm = pass ? W2 : W1;
#pragma unroll 1
        for (int k0 = 0; k0 < dim; k0 += BK) {
            // --- stage A (gather in pass 0) and B tiles into smem, transposed
#pragma unroll
            for (int h = 0; h < 2; ++h) {
                const int m = r0 + h * 64;

                float4 av = make_float4(0.f, 0.f, 0.f, 0.f);
                const float* p = pass ? aS[h] : aG[h];
                if (valid[h])
                    av = *reinterpret_cast<const float4*>(p + k0 + c4);
                As[c4 + 0][m] = av.x;
                As[c4 + 1][m] = av.y;
                As[c4 + 2][m] = av.z;
                As[c4 + 3][m] = av.w;

                float4 bv = *reinterpret_cast<const float4*>(
                    Wm + (size_t)(nBase + m) * (size_t)dim + k0 + c4);
                Bs[c4 + 0][m] = bv.x;
                Bs[c4 + 1][m] = bv.y;
                Bs[c4 + 2][m] = bv.z;
                Bs[c4 + 3][m] = bv.w;
            }
            __syncthreads();

            // --- compute: 16 k-steps, 32 fma.rn.f32x2 each
#pragma unroll
            for (int kk = 0; kk < BK; ++kk) {
                const ulonglong2* ap =
                    reinterpret_cast<const ulonglong2*>(&As[kk][ty * 8]);
                ulonglong2 av0 = ap[0];
                ulonglong2 av1 = ap[1];
                unsigned long long a2[4] = {av0.x, av0.y, av1.x, av1.y};

                float4 bv0 = *reinterpret_cast<const float4*>(&Bs[kk][tx * 8]);
                float4 bv1 = *reinterpret_cast<const float4*>(&Bs[kk][tx * 8 + 4]);
                unsigned long long b2[8];
                b2[0] = pack2(bv0.x, bv0.x);
                b2[1] = pack2(bv0.y, bv0.y);
                b2[2] = pack2(bv0.z, bv0.z);
                b2[3] = pack2(bv0.w, bv0.w);
                b2[4] = pack2(bv1.x, bv1.x);
                b2[5] = pack2(bv1.y, bv1.y);
                b2[6] = pack2(bv1.z, bv1.z);
                b2[7] = pack2(bv1.w, bv1.w);

#pragma unroll
                for (int i = 0; i < 4; ++i)
#pragma unroll
                    for (int j = 0; j < 8; ++j)
                        fma2(C2[i][j], a2[i], b2[j]);
            }
            __syncthreads();
        }
    }

    // --- epilogue: add bias, scatter to out[idx[m]]
    float bias[8];
#pragma unroll
    for (int j = 0; j < 8; ++j) {
        int n = nBase + tx * 8 + j;
        bias[j] = b1[n] + b2[n];
    }

#pragma unroll
    for (int i = 0; i < 4; ++i) {
        float lo[8], hi[8];
#pragma unroll
        for (int j = 0; j < 8; ++j) unpack2(C2[i][j], lo[j], hi[j]);

        int m0 = tileM + ty * 8 + 2 * i;
        if (m0 < Mrows) {
            long long g = load_idx(idx, m0, is64);
            float* o = out + (size_t)g * (size_t)dim + nBase + tx * 8;
            float4 v0 = make_float4(lo[0] + bias[0], lo[1] + bias[1],
                                    lo[2] + bias[2], lo[3] + bias[3]);
            float4 v1 = make_float4(lo[4] + bias[4], lo[5] + bias[5],
                                    lo[6] + bias[6], lo[7] + bias[7]);
            reinterpret_cast<float4*>(o)[0] = v0;
            reinterpret_cast<float4*>(o)[1] = v1;
        }
        if (m0 + 1 < Mrows) {
            long long g = load_idx(idx, m0 + 1, is64);
            float* o = out + (size_t)g * (size_t)dim + nBase + tx * 8;
            float4 v0 = make_float4(hi[0] + bias[0], hi[1] + bias[1],
                                    hi[2] + bias[2], hi[3] + bias[3]);
            float4 v1 = make_float4(hi[4] + bias[4], hi[5] + bias[5],
                                    hi[6] + bias[6], hi[7] + bias[7]);
            reinterpret_cast<float4*>(o)[0] = v0;
            reinterpret_cast<float4*>(o)[1] = v1;
        }
    }
}

extern "C" void kernel_launch(void* const* d_in, const int* in_sizes, int n_in,
                              void* d_out, int out_size) {
    const float* h_full = (const float*)d_in[0];
    const float* h_sub  = (const float*)d_in[1];
    const float* W1     = (const float*)d_in[2];
    const float* b1     = (const float*)d_in[3];
    const float* W2     = (const float*)d_in[4];
    const float* b2     = (const float*)d_in[5];
    const void*  idx    = d_in[6];
    float*       out    = (float*)d_out;

    const int dim   = in_sizes[3];          // bias length = DIM (256)
    const int Mrows = in_sizes[1] / dim;    // pooled node count
    const long long Nfull = (long long)in_sizes[0] / dim;

    // Stage 0: detect idx dtype (int32 vs int64) on device.
    detect_idx_kernel<<<1, 1>>>(idx, Mrows, Nfull);

    // Stage 1: bulk copy h_full -> out (D2D async memcpy, capturable).
    cudaMemcpyAsync(out, h_full, (size_t)out_size * sizeof(float),
                    cudaMemcpyDeviceToDevice, 0);

    // Stage 2: fused dual-GEMM + bias + scatter overwrite of pooled rows.
    dim3 grid((unsigned)((Mrows + BM - 1) / BM), (unsigned)(dim / BN));
    merge_gemm<<<grid, THREADS>>>(h_full, h_sub, W1, b1, W2, b2, idx, out,
                                  Mrows, dim);
}

// round 4
// speedup vs baseline: 2.2744x; 2.2744x over previous
#include <cuda_runtime.h>
#include <cuda_bf16.h>
#include <cstdint>

// ---------------------------------------------------------------------------
// NodeUnpool via mma.sync (HMMA, bf16 3-product split):
//   out = h_full;  out[idx] = h_full[idx]@W1^T + b1 + h_sub@W2^T + b2
// C[M,256] = [h_full[idx] | h_sub] @ [W1 | W2]^T   (K = 512 concat)
// tcgen05 unavailable (harness PTX target = compute_103, no 'a' features).
// ---------------------------------------------------------------------------

#define DIM      256
#define BM       128
#define BN       128
#define KC       64
#define THREADS  256
#define STRIDE_B 144            // smem row stride in bytes (72 halves)

// smem layout (bytes)
#define SM_ROWIDX 0             // int[128]
#define SM_BIAS   512           // float[128]
#define SM_AH     1024          // [128][72] bf16 = 18432
#define SM_AL     (SM_AH + 18432)
#define SM_B0     (SM_AL + 18432)     // B stages start: 37888
#define B_STAGE   36864               // Bh(18432)+Bl(18432) per stage
#define B_LOFF    18432
#define SM_TOTAL  (SM_B0 + 2 * B_STAGE)   // 111616

__device__ int g_idx_is64;
__device__ __align__(16) __nv_bfloat16 g_Bh[256 * 512];   // [n][kcat]
__device__ __align__(16) __nv_bfloat16 g_Bl[256 * 512];

// ---------------- helpers ----------------
__device__ __forceinline__ uint32_t smem_u32(const void* p) {
    uint32_t a;
    asm("{ .reg .u64 t; cvta.to.shared.u64 t, %1; cvt.u32.u64 %0, t; }"
        : "=r"(a) : "l"(p));
    return a;
}
__device__ __forceinline__ void cp_async16(uint32_t dst, const void* src) {
    asm volatile("cp.async.cg.shared.global [%0], [%1], 16;"
                 :: "r"(dst), "l"(src) : "memory");
}
__device__ __forceinline__ void cp_commit() {
    asm volatile("cp.async.commit_group;" ::: "memory");
}
__device__ __forceinline__ void cp_wait0() {
    asm volatile("cp.async.wait_group 0;" ::: "memory");
}
__device__ __forceinline__ void ldsm4(uint32_t* r, uint32_t addr) {
    asm volatile("ldmatrix.sync.aligned.m8n8.x4.shared.b16 {%0,%1,%2,%3}, [%4];"
                 : "=r"(r[0]), "=r"(r[1]), "=r"(r[2]), "=r"(r[3]) : "r"(addr));
}
__device__ __forceinline__ uint32_t lds32(uint32_t addr) {
    uint32_t v;
    asm volatile("ld.shared.b32 %0, [%1];" : "=r"(v) : "r"(addr));
    return v;
}
__device__ __forceinline__ void mma16816(float* d, const uint32_t* a,
                                         uint32_t b0, uint32_t b1) {
    asm volatile(
        "mma.sync.aligned.m16n8k16.row.col.f32.bf16.bf16.f32 "
        "{%0,%1,%2,%3}, {%4,%5,%6,%7}, {%8,%9}, {%0,%1,%2,%3};"
        : "+f"(d[0]), "+f"(d[1]), "+f"(d[2]), "+f"(d[3])
        : "r"(a[0]), "r"(a[1]), "r"(a[2]), "r"(a[3]), "r"(b0), "r"(b1));
}

// ---------------- idx dtype detection ----------------
__device__ __forceinline__ long long load_idx(const void* idx, int r, int is64) {
    if (is64) return reinterpret_cast<const long long*>(idx)[r];
    return (long long)reinterpret_cast<const int*>(idx)[r];
}
__global__ void detect_idx_kernel(const void* idx, int Mrows, long long Nfull) {
    const long long* p64 = reinterpret_cast<const long long*>(idx);
    int n = Mrows / 2;
    if (n > 8) n = 8;
    bool ok64 = (n > 0);
    for (int i = 0; i < n; ++i) {
        long long v = p64[i];
        if (v < 0 || v >= Nfull) { ok64 = false; break; }
    }
    g_idx_is64 = ok64 ? 1 : 0;
}

// ---------------- W -> bf16 hi/lo, [n][kcat] ----------------
__global__ void convert_W(const float* __restrict__ W1, const float* __restrict__ W2) {
    int t = blockIdx.x * blockDim.x + threadIdx.x;   // 256*512
    if (t >= 256 * 512) return;
    int n    = t >> 9;
    int kcat = t & 511;
    float x = (kcat < DIM) ? W1[n * DIM + kcat] : W2[n * DIM + (kcat - DIM)];
    __nv_bfloat16 h = __float2bfloat16(x);
    __nv_bfloat16 l = __float2bfloat16(x - __bfloat162float(h));
    g_Bh[t] = h;
    g_Bl[t] = l;
}

// ---------------- main GEMM ----------------
__global__ __launch_bounds__(THREADS)
void merge_gemm_mma(const float* __restrict__ h_full,
                    const float* __restrict__ h_sub,
                    const float* __restrict__ b1,
                    const float* __restrict__ b2,
                    const void*  __restrict__ idx,
                    float* __restrict__ out,
                    int Mrows)
{
    extern __shared__ __align__(16) char smem[];
    const uint32_t sbase = smem_u32(smem);

    const int tid   = threadIdx.x;
    const int wid   = tid >> 5;
    const int lid   = tid & 31;
    const int tileM = blockIdx.x * BM;
    const int nBase = blockIdx.y * BN;
    const int warpM = (wid & 3) * 32;
    const int warpN = (wid >> 2) * 64;

    int*   rowidx = (int*)(smem + SM_ROWIDX);
    float* biasS  = (float*)(smem + SM_BIAS);

    const int is64 = g_idx_is64;
    if (tid < BM) {
        int m = tileM + tid;
        rowidx[tid] = (m < Mrows) ? (int)load_idx(idx, m, is64) : 0;
        biasS[tid]  = b1[nBase + tid] + b2[nBase + tid];
    }
    __syncthreads();

    // ---- B stage fill via cp.async (chunk c -> stage st)
    auto issueB = [&](int c, int st) {
        uint32_t dbase = sbase + SM_B0 + st * B_STAGE;
#pragma unroll
        for (int j = 0; j < 4; ++j) {
            int id  = tid + j * THREADS;     // 0..1023
            int row = id >> 3;               // 0..127
            int seg = id & 7;                // 16B segment
            uint32_t dst = dbase + row * STRIDE_B + seg * 16;
            size_t srcOff = (((size_t)(nBase + row) << 9) + c * KC + seg * 8) * 2;
            cp_async16(dst,          (const char*)g_Bh + srcOff);
            cp_async16(dst + B_LOFF, (const char*)g_Bl + srcOff);
        }
    };

    // ---- A chunk gather into regs
    auto loadA = [&](float4* dst, int c) {
        const bool fromFull = (c < 4);
        const int  kb = (c & 3) * KC;
#pragma unroll
        for (int j = 0; j < 8; ++j) {
            int id = tid + j * THREADS;      // 0..2047
            int r  = id >> 4;                // 0..127
            int c4 = (id & 15) << 2;         // 0..60
            const float* src;
            if (fromFull) {
                src = h_full + (size_t)rowidx[r] * DIM;
            } else {
                int m = tileM + r;
                if (m >= Mrows) m = Mrows - 1;
                src = h_sub + (size_t)m * DIM;
            }
            dst[j] = *(const float4*)(src + kb + c4);
        }
    };

    // ---- A regs -> bf16 hi/lo smem
    auto storeA = [&](const float4* v) {
#pragma unroll
        for (int j = 0; j < 8; ++j) {
            int id = tid + j * THREADS;
            int r  = id >> 4;
            int c4 = (id & 15) << 2;
            float4 q = v[j];
            __nv_bfloat16 hx = __float2bfloat16(q.x);
            __nv_bfloat16 hy = __float2bfloat16(q.y);
            __nv_bfloat16 hz = __float2bfloat16(q.z);
            __nv_bfloat16 hw = __float2bfloat16(q.w);
            __nv_bfloat162 h01; h01.x = hx; h01.y = hy;
            __nv_bfloat162 h23; h23.x = hz; h23.y = hw;
            __nv_bfloat162 l01, l23;
            l01.x = __float2bfloat16(q.x - __bfloat162float(hx));
            l01.y = __float2bfloat16(q.y - __bfloat162float(hy));
            l23.x = __float2bfloat16(q.z - __bfloat162float(hz));
            l23.y = __float2bfloat16(q.w - __bfloat162float(hw));
            uint32_t off = r * STRIDE_B + c4 * 2;
            *(uint2*)(smem + SM_AH + off) =
                make_uint2(*(uint32_t*)&h01, *(uint32_t*)&h23);
            *(uint2*)(smem + SM_AL + off) =
                make_uint2(*(uint32_t*)&l01, *(uint32_t*)&l23);
        }
    };

    float acc[2][8][4];
#pragma unroll
    for (int mt = 0; mt < 2; ++mt)
#pragma unroll
        for (int nt = 0; nt < 8; ++nt)
#pragma unroll
            for (int q = 0; q < 4; ++q) acc[mt][nt][q] = 0.f;

    // ---- compute one KC=64 chunk from stage st
    auto compute = [&](int st) {
        const uint32_t aH = sbase + SM_AH;
        const uint32_t bB = sbase + SM_B0 + st * B_STAGE;
#pragma unroll
        for (int kk = 0; kk < 4; ++kk) {
            uint32_t ah[2][4], al[2][4];
#pragma unroll
            for (int mt = 0; mt < 2; ++mt) {
                uint32_t ra = (uint32_t)(warpM + mt * 16 + (lid & 15)) * STRIDE_B
                            + (kk * 16 + (lid >> 4) * 8) * 2;
                ldsm4(ah[mt], aH + ra);
                ldsm4(al[mt], aH + 18432 + ra);
            }
#pragma unroll
            for (int nt = 0; nt < 8; ++nt) {
                uint32_t rb = bB + (uint32_t)(warpN + nt * 8 + (lid >> 2)) * STRIDE_B
                            + (kk * 16 + (lid & 3) * 2) * 2;
                uint32_t bh0 = lds32(rb),          bh1 = lds32(rb + 16);
                uint32_t bl0 = lds32(rb + B_LOFF), bl1 = lds32(rb + B_LOFF + 16);
#pragma unroll
                for (int mt = 0; mt < 2; ++mt) {
                    mma16816(acc[mt][nt], ah[mt], bh0, bh1);
                    mma16816(acc[mt][nt], ah[mt], bl0, bl1);
                    mma16816(acc[mt][nt], al[mt], bh0, bh1);
                }
            }
        }
    };

    // ---- prologue: chunk 0
    float4 aPre[8];
    issueB(0, 0);
    cp_commit();
    loadA(aPre, 0);
    storeA(aPre);
    cp_wait0();
    __syncthreads();

    // ---- main loop over 8 K-chunks (2 passes x 4)
#pragma unroll 1
    for (int c = 0; c < 8; ++c) {
        const int st = c & 1;
        if (c < 7) {
            issueB(c + 1, st ^ 1);
            cp_commit();
            loadA(aPre, c + 1);
        }
        compute(st);
        __syncthreads();                 // everyone done reading A smem + B[st]
        if (c < 7) {
            storeA(aPre);
            cp_wait0();
        }
        __syncthreads();                 // next A/B staged
    }

    // ---- epilogue: bias add + scatter from register accumulators
    {
        const int r0 = lid >> 2;            // 0..7
        const int nc = (lid & 3) * 2;       // 0,2,4,6
#pragma unroll
        for (int mt = 0; mt < 2; ++mt) {
#pragma unroll
            for (int half = 0; half < 2; ++half) {
                int row = warpM + mt * 16 + r0 + half * 8;   // local 0..127
                int mg  = tileM + row;
                if (mg < Mrows) {
                    float* orow = out + (size_t)rowidx[row] * DIM + nBase + warpN;
#pragma unroll
                    for (int nt = 0; nt < 8; ++nt) {
                        float2 bv = *(const float2*)&biasS[warpN + nt * 8 + nc];
                        float2 v;
                        v.x = acc[mt][nt][half * 2 + 0] + bv.x;
                        v.y = acc[mt][nt][half * 2 + 1] + bv.y;
                        *(float2*)(orow + nt * 8 + nc) = v;
                    }
                }
            }
        }
    }
}

// ---------------- launch ----------------
extern "C" void kernel_launch(void* const* d_in, const int* in_sizes, int n_in,
                              void* d_out, int out_size) {
    const float* h_full = (const float*)d_in[0];
    const float* h_sub  = (const float*)d_in[1];
    const float* W1     = (const float*)d_in[2];
    const float* b1     = (const float*)d_in[3];
    const float* W2     = (const float*)d_in[4];
    const float* b2     = (const float*)d_in[5];
    const void*  idx    = d_in[6];
    float*       out    = (float*)d_out;

    const int dim   = in_sizes[3];
    const int Mrows = in_sizes[1] / dim;
    const long long Nfull = (long long)in_sizes[0] / dim;

    cudaFuncSetAttribute(merge_gemm_mma,
                         cudaFuncAttributeMaxDynamicSharedMemorySize, SM_TOTAL);

    detect_idx_kernel<<<1, 1>>>(idx, Mrows, Nfull);
    convert_W<<<(256 * 512 + 255) / 256, 256>>>(W1, W2);

    cudaMemcpyAsync(out, h_full, (size_t)out_size * sizeof(float),
                    cudaMemcpyDeviceToDevice, 0);

    dim3 grid((unsigned)((Mrows + BM - 1) / BM), (unsigned)(dim / BN));
    merge_gemm_mma<<<grid, THREADS, SM_TOTAL>>>(h_full, h_sub, b1, b2, idx,
                                                out, Mrows);
}